// round 3
// baseline (speedup 1.0000x reference)
#include <cuda_runtime.h>
#include <cuda_bf16.h>
#include <cstdint>

// LoRA low-rank fused kernel, round 2: occupancy-oriented rebalance.
//   t[m][r]  = sum_i x[m][i] * A[r][i]
//   out[m][o]= 2 * sum_r t[m][r] * B[o][r] + bias[o]
//
// 4 rows per warp (2 packed m-pairs) -> 64 accumulator regs instead of 128.
// __launch_bounds__(128,4) forces <=128 regs -> 4 blocks/SM -> 512-block grid
// is one full wave on 148 SMs.

#define IN_F   4096
#define OUT_F  4096
#define RANK   16
#define M_TOT  8192
#define CK     512          // A chunk (i-dimension) staged in smem
#define MTILE  16           // m rows per block
#define RPW    4            // m rows per warp (4 warps/block)
#define NMP    2            // packed m-pairs per warp

__device__ __forceinline__ unsigned long long pk2(float lo, float hi) {
    unsigned long long r;
    asm("mov.b64 %0, {%1,%2};" : "=l"(r) : "f"(lo), "f"(hi));
    return r;
}
__device__ __forceinline__ void fma2(unsigned long long &d,
                                     unsigned long long a,
                                     unsigned long long b) {
    asm("fma.rn.f32x2 %0, %1, %2, %0;" : "+l"(d) : "l"(a), "l"(b));
}
__device__ __forceinline__ float2 up2(unsigned long long v) {
    float2 f;
    asm("mov.b64 {%0,%1}, %2;" : "=f"(f.x), "=f"(f.y) : "l"(v));
    return f;
}

__global__ __launch_bounds__(128, 4)
void lora_fused_kernel(const float* __restrict__ x,
                       const float* __restrict__ A,      // [16, 4096]
                       const float* __restrict__ B,      // [4096, 16]
                       const float* __restrict__ bias,   // [4096]
                       float* __restrict__ out)
{
    __shared__ float As[RANK][CK];       // staged A chunk
    __shared__ float t_s[MTILE][RANK];   // per-block t, scaled by 2

    const int tid  = threadIdx.x;
    const int lane = tid & 31;
    const int w    = tid >> 5;           // warp id 0..3
    const int mbase = blockIdx.x * MTILE;

    // ---------------- Phase 1: t = x @ A^T ----------------
    unsigned long long acc[NMP][RANK];
    #pragma unroll
    for (int mp = 0; mp < NMP; ++mp)
        #pragma unroll
        for (int r = 0; r < RANK; ++r)
            acc[mp][r] = 0ull;

    const float* xw = x + (size_t)(mbase + w * RPW) * IN_F;

    for (int i0 = 0; i0 < IN_F; i0 += CK) {
        __syncthreads();
        // stage A chunk: As[r][il] = A[r][i0+il], vectorized float4
        for (int k = tid; k < RANK * (CK / 4); k += 128) {
            const int r  = k >> 7;            // CK/4 == 128
            const int il = (k & 127) << 2;
            *(float4*)&As[r][il] = *(const float4*)&A[r * IN_F + i0 + il];
        }
        __syncthreads();

        #pragma unroll
        for (int s = 0; s < CK / 128; ++s) {
            const int il = s * 128 + lane * 4;

            // load the warp's 4 x-rows (one float4 each), pack into m-pair operands
            unsigned long long xp[NMP][4];
            #pragma unroll
            for (int mp = 0; mp < NMP; ++mp) {
                const float4 xa = *(const float4*)(xw + (size_t)(2 * mp)     * IN_F + i0 + il);
                const float4 xb = *(const float4*)(xw + (size_t)(2 * mp + 1) * IN_F + i0 + il);
                xp[mp][0] = pk2(xa.x, xb.x);
                xp[mp][1] = pk2(xa.y, xb.y);
                xp[mp][2] = pk2(xa.z, xb.z);
                xp[mp][3] = pk2(xa.w, xb.w);
            }

            #pragma unroll
            for (int r = 0; r < RANK; ++r) {
                const float4 a4 = *(const float4*)&As[r][il];
                const float av[4] = {a4.x, a4.y, a4.z, a4.w};
                #pragma unroll
                for (int j = 0; j < 4; ++j) {
                    const unsigned long long aa = pk2(av[j], av[j]);
                    #pragma unroll
                    for (int mp = 0; mp < NMP; ++mp)
                        fma2(acc[mp][r], xp[mp][j], aa);
                }
            }
        }
    }

    // warp-reduce packed accumulators; lane 0 writes t (x2 scaling folded in)
    #pragma unroll
    for (int mp = 0; mp < NMP; ++mp) {
        #pragma unroll
        for (int r = 0; r < RANK; ++r) {
            float2 f = up2(acc[mp][r]);
            #pragma unroll
            for (int off = 16; off; off >>= 1) {
                f.x += __shfl_down_sync(0xffffffffu, f.x, off);
                f.y += __shfl_down_sync(0xffffffffu, f.y, off);
            }
            if (lane == 0) {
                t_s[w * RPW + 2 * mp][r]     = 2.0f * f.x;
                t_s[w * RPW + 2 * mp + 1][r] = 2.0f * f.y;
            }
        }
    }
    __syncthreads();

    // ---------------- Phase 2: out = t @ B^T + bias ----------------
    unsigned long long tp[NMP][RANK];
    #pragma unroll
    for (int mp = 0; mp < NMP; ++mp)
        #pragma unroll
        for (int r = 0; r < RANK; ++r)
            tp[mp][r] = pk2(t_s[w * RPW + 2 * mp][r], t_s[w * RPW + 2 * mp + 1][r]);

    float* outw = out + (size_t)(mbase + w * RPW) * OUT_F;

    for (int ob = 0; ob < OUT_F; ob += 32) {
        const int o = ob + lane;
        const float4* Bp = (const float4*)(B + o * RANK);
        const float4 b0 = Bp[0], b1 = Bp[1], b2 = Bp[2], b3 = Bp[3];
        const float bv[16] = {b0.x, b0.y, b0.z, b0.w,
                              b1.x, b1.y, b1.z, b1.w,
                              b2.x, b2.y, b2.z, b2.w,
                              b3.x, b3.y, b3.z, b3.w};
        const float bi = __ldg(bias + o);

        unsigned long long a2[NMP];
        #pragma unroll
        for (int mp = 0; mp < NMP; ++mp) a2[mp] = pk2(bi, bi);

        #pragma unroll
        for (int r = 0; r < RANK; ++r) {
            const unsigned long long bb = pk2(bv[r], bv[r]);
            #pragma unroll
            for (int mp = 0; mp < NMP; ++mp)
                fma2(a2[mp], tp[mp][r], bb);
        }

        #pragma unroll
        for (int mp = 0; mp < NMP; ++mp) {
            const float2 v = up2(a2[mp]);
            outw[(size_t)(2 * mp)     * OUT_F + o] = v.x;
            outw[(size_t)(2 * mp + 1) * OUT_F + o] = v.y;
        }
    }
}

extern "C" void kernel_launch(void* const* d_in, const int* in_sizes, int n_in,
                              void* d_out, int out_size) {
    const float* x    = (const float*)d_in[0];   // [4,2048,4096] -> [8192,4096]
    const float* A    = (const float*)d_in[1];   // [16,4096]
    const float* B    = (const float*)d_in[2];   // [4096,16]
    const float* bias = (const float*)d_in[3];   // [4096]
    float* out = (float*)d_out;                  // [8192,4096]

    lora_fused_kernel<<<M_TOT / MTILE, 128>>>(x, A, B, bias, out);
}

// round 4
// speedup vs baseline: 1.1076x; 1.1076x over previous
#include <cuda_runtime.h>
#include <cuda_bf16.h>
#include <cstdint>

// LoRA low-rank, 3-kernel pipeline:
//   prep   : At[k][r] = 2 * A[r][k]          (scaling folded)
//   phase1 : tp[ks][m][r] = sum_{k in slice} x[m][k] * At[k][r]
//   phase2 : out[m][o] = sum_r (sum_ks tp) * B[o][r] + bias[o]

#define IN_F   4096
#define OUT_F  4096
#define RANK   16
#define M_TOT  8192

#define MT     64                 // m rows per phase-1 block
#define KSPLIT 4
#define KRANGE (IN_F / KSPLIT)    // 1024
#define KC     64                 // k chunk staged in smem
#define NCH    (KRANGE / KC)      // 16
#define XPITCH 66                 // xs row pitch in floats (conflict-free transpose)

__device__ __align__(16) float g_At[IN_F * RANK];            // 256 KB
__device__ __align__(16) float g_tp[KSPLIT][M_TOT][RANK];    // 2 MB partials

typedef unsigned long long u64;

__device__ __forceinline__ u64 pk2(float lo, float hi) {
    u64 r; asm("mov.b64 %0, {%1,%2};" : "=l"(r) : "f"(lo), "f"(hi)); return r;
}
__device__ __forceinline__ void fma2(u64 &d, u64 a, u64 b) {
    asm("fma.rn.f32x2 %0, %1, %2, %0;" : "+l"(d) : "l"(a), "l"(b));
}
__device__ __forceinline__ float2 up2(u64 v) {
    float2 f; asm("mov.b64 {%0,%1}, %2;" : "=f"(f.x), "=f"(f.y) : "l"(v)); return f;
}

// ---------------- prep: At = 2 * A^T ----------------
__global__ void prep_At(const float* __restrict__ A) {
    const int e = blockIdx.x * 256 + threadIdx.x;   // 65536 elems
    const int k = e >> 4, r = e & 15;
    g_At[e] = 2.0f * A[r * IN_F + k];
}

// ---------------- phase 1 ----------------
__global__ __launch_bounds__(256, 2)
void lora_phase1(const float* __restrict__ x) {
    __shared__ float  xs[2][KC][XPITCH];     // k-major x tile, padded rows
    __shared__ float4 as[2][KC * 4];         // At chunk, 16 floats (4 float4) per k

    const int tid  = threadIdx.x;
    const int lane = tid & 31;
    const int w    = tid >> 5;                       // 8 warps
    const int mt   = blockIdx.x & (M_TOT / MT - 1);  // 0..127
    const int ks   = blockIdx.x >> 7;                // 0..3
    const int mbase = mt * MT;
    const int k0    = ks * KRANGE;

    // staging geometry: thread -> (m row, k-float4 lane); conflict-free STS with pad 66
    const int sm  = tid >> 2;        // 0..63
    const int sk4 = tid & 3;         // 0..3
    const float* xrow = x + (size_t)(mbase + sm) * IN_F + k0;

    u64 acc[2][8];
    #pragma unroll
    for (int mp = 0; mp < 2; ++mp)
        #pragma unroll
        for (int rp = 0; rp < 8; ++rp) acc[mp][rp] = 0ull;

    float4 xr[4], ar;

    // prologue: load + STS chunk 0
    #pragma unroll
    for (int it = 0; it < 4; ++it)
        xr[it] = *(const float4*)(xrow + (sk4 + 4 * it) * 4);
    ar = *(const float4*)(g_At + (size_t)(k0) * RANK + tid * 4);

    #pragma unroll
    for (int it = 0; it < 4; ++it) {
        const int kk = 4 * (sk4 + 4 * it);
        xs[0][kk + 0][sm] = xr[it].x;
        xs[0][kk + 1][sm] = xr[it].y;
        xs[0][kk + 2][sm] = xr[it].z;
        xs[0][kk + 3][sm] = xr[it].w;
    }
    as[0][tid] = ar;
    __syncthreads();

    for (int c = 0; c < NCH; ++c) {
        const int buf = c & 1;

        if (c + 1 < NCH) {   // prefetch next chunk into registers
            const int kc1 = (c + 1) * KC;
            #pragma unroll
            for (int it = 0; it < 4; ++it)
                xr[it] = *(const float4*)(xrow + kc1 + (sk4 + 4 * it) * 4);
            ar = *(const float4*)(g_At + (size_t)(k0 + kc1) * RANK + tid * 4);
        }

        // compute: warp w handles k = w*8 .. w*8+7 of this chunk
        #pragma unroll
        for (int kk = 0; kk < KC / 8; ++kk) {
            const int k = w * (KC / 8) + kk;
            const float2 xv = *(const float2*)&xs[buf][k][2 * lane];
            const u64 xd0 = pk2(xv.x, xv.x);
            const u64 xd1 = pk2(xv.y, xv.y);
            const ulonglong2* ap = (const ulonglong2*)&as[buf][k * 4];
            const ulonglong2 a01 = ap[0], a23 = ap[1];
            fma2(acc[0][0], xd0, a01.x); fma2(acc[1][0], xd1, a01.x);
            fma2(acc[0][1], xd0, a01.y); fma2(acc[1][1], xd1, a01.y);
            fma2(acc[0][2], xd0, a23.x); fma2(acc[1][2], xd1, a23.x);
            fma2(acc[0][3], xd0, a23.y); fma2(acc[1][3], xd1, a23.y);
            const ulonglong2 a45 = ap[2], a67 = ap[3];
            fma2(acc[0][4], xd0, a45.x); fma2(acc[1][4], xd1, a45.x);
            fma2(acc[0][5], xd0, a45.y); fma2(acc[1][5], xd1, a45.y);
            fma2(acc[0][6], xd0, a67.x); fma2(acc[1][6], xd1, a67.x);
            fma2(acc[0][7], xd0, a67.y); fma2(acc[1][7], xd1, a67.y);
        }

        if (c + 1 < NCH) {
            const int nb = (c + 1) & 1;
            #pragma unroll
            for (int it = 0; it < 4; ++it) {
                const int kk = 4 * (sk4 + 4 * it);
                xs[nb][kk + 0][sm] = xr[it].x;
                xs[nb][kk + 1][sm] = xr[it].y;
                xs[nb][kk + 2][sm] = xr[it].z;
                xs[nb][kk + 3][sm] = xr[it].w;
            }
            as[nb][tid] = ar;
        }
        __syncthreads();
    }

    // deterministic cross-warp reduction in smem (reuse xs: 8448 floats >= 8192)
    float* tredf = &xs[0][0][0];
    #pragma unroll
    for (int mp = 0; mp < 2; ++mp) {
        const int m = 2 * lane + mp;
        const int base = w * 1024 + m * 16;
        #pragma unroll
        for (int rp = 0; rp < 8; ++rp) {
            const float2 f = up2(acc[mp][rp]);
            tredf[base + ((2 * rp     + lane) & 15)] = f.x;  // lane-swizzled col
            tredf[base + ((2 * rp + 1 + lane) & 15)] = f.y;
        }
    }
    __syncthreads();

    {
        const int m  = tid >> 2;            // 0..63
        const int r0 = (tid & 3) * 4;
        const int lw = m >> 1;              // writer's lane
        float s[4];
        #pragma unroll
        for (int j = 0; j < 4; ++j) {
            const int cr = (r0 + j + lw) & 15;
            float v = 0.0f;
            #pragma unroll
            for (int w8 = 0; w8 < 8; ++w8)
                v += tredf[w8 * 1024 + m * 16 + cr];
            s[j] = v;
        }
        *(float4*)&g_tp[ks][mbase + m][r0] = make_float4(s[0], s[1], s[2], s[3]);
    }
}

// ---------------- phase 2 ----------------
__global__ __launch_bounds__(256, 2)
void lora_phase2(const float* __restrict__ B,
                 const float* __restrict__ bias,
                 float* __restrict__ out) {
    const int tid  = threadIdx.x;
    const int lane = tid & 31;
    const int w    = tid >> 5;
    const int m0   = blockIdx.x * 32 + w * 4;    // 4 m rows per thread (whole warp)

    // sum 4 partials for the 4 rows, pack rank-pairs
    float4 tf[4][4];
    #pragma unroll
    for (int mm = 0; mm < 4; ++mm)
        #pragma unroll
        for (int q = 0; q < 4; ++q) tf[mm][q] = make_float4(0, 0, 0, 0);

    #pragma unroll
    for (int s = 0; s < KSPLIT; ++s)
        #pragma unroll
        for (int mm = 0; mm < 4; ++mm) {
            const float4* p = (const float4*)&g_tp[s][m0 + mm][0];
            #pragma unroll
            for (int q = 0; q < 4; ++q) {
                const float4 v = p[q];
                tf[mm][q].x += v.x; tf[mm][q].y += v.y;
                tf[mm][q].z += v.z; tf[mm][q].w += v.w;
            }
        }

    u64 tu[4][8];
    #pragma unroll
    for (int mm = 0; mm < 4; ++mm)
        #pragma unroll
        for (int q = 0; q < 4; ++q) {
            tu[mm][2 * q]     = pk2(tf[mm][q].x, tf[mm][q].y);
            tu[mm][2 * q + 1] = pk2(tf[mm][q].z, tf[mm][q].w);
        }

    for (int ob = 0; ob < OUT_F; ob += 32) {
        const int o = ob + lane;
        const ulonglong2* Br = (const ulonglong2*)(B + (size_t)o * RANK);
        const ulonglong2 b0 = __ldg(Br), b1 = __ldg(Br + 1),
                         b2 = __ldg(Br + 2), b3 = __ldg(Br + 3);
        const u64 bu[8] = { b0.x, b0.y, b1.x, b1.y, b2.x, b2.y, b3.x, b3.y };
        const float bi = __ldg(bias + o);

        #pragma unroll
        for (int mm = 0; mm < 4; ++mm) {
            u64 a = 0ull;
            #pragma unroll
            for (int rp = 0; rp < 8; ++rp) fma2(a, tu[mm][rp], bu[rp]);
            const float2 f = up2(a);
            out[(size_t)(m0 + mm) * OUT_F + o] = f.x + f.y + bi;
        }
    }
}

extern "C" void kernel_launch(void* const* d_in, const int* in_sizes, int n_in,
                              void* d_out, int out_size) {
    const float* x    = (const float*)d_in[0];   // [8192, 4096]
    const float* A    = (const float*)d_in[1];   // [16, 4096]
    const float* B    = (const float*)d_in[2];   // [4096, 16]
    const float* bias = (const float*)d_in[3];   // [4096]
    float* out = (float*)d_out;                  // [8192, 4096]

    prep_At<<<IN_F * RANK / 256, 256>>>(A);
    lora_phase1<<<(M_TOT / MT) * KSPLIT, 256>>>(x);
    lora_phase2<<<M_TOT / 32, 256>>>(B, bias, out);
}

// round 5
// speedup vs baseline: 1.7404x; 1.5713x over previous
#include <cuda_runtime.h>
#include <cuda_bf16.h>
#include <cstdint>

// LoRA low-rank, 3-kernel pipeline (round 4):
//   prep   : At[k][r] = 2 * A[r][k]
//   phase1 : tp[ks][m][r] = sum_{k in slice} x[m][k] * At[k][r]
//   phase2 : out[m][o] = sum_r (sum_ks tp) * B[o][r] + bias[o]
// Phase-2 redesigned: B rows live in per-thread registers (loaded once),
// t broadcast from smem pre-duplicated -> no more 16-line LDG replays.

#define IN_F   4096
#define OUT_F  4096
#define RANK   16
#define M_TOT  8192

#define MT     64                 // m rows per phase-1 block
#define KSPLIT 8
#define KRANGE (IN_F / KSPLIT)    // 512
#define KC     64                 // k chunk staged in smem
#define NCH    (KRANGE / KC)      // 8
#define XPITCH 66

#define OTPB   1024               // o columns per phase-2 block
#define MSLAB  128                // m rows per phase-2 block

__device__ __align__(16) float g_At[IN_F * RANK];            // 256 KB
__device__ __align__(16) float g_tp[KSPLIT][M_TOT][RANK];    // 4 MB partials

typedef unsigned long long u64;

__device__ __forceinline__ u64 pk2(float lo, float hi) {
    u64 r; asm("mov.b64 %0, {%1,%2};" : "=l"(r) : "f"(lo), "f"(hi)); return r;
}
__device__ __forceinline__ void fma2(u64 &d, u64 a, u64 b) {
    asm("fma.rn.f32x2 %0, %1, %2, %0;" : "+l"(d) : "l"(a), "l"(b));
}
__device__ __forceinline__ float2 up2(u64 v) {
    float2 f; asm("mov.b64 {%0,%1}, %2;" : "=f"(f.x), "=f"(f.y) : "l"(v)); return f;
}

// ---------------- prep: At = 2 * A^T (coalesced reads) ----------------
__global__ void prep_At(const float* __restrict__ A) {
    const int i  = blockIdx.x * 256 + threadIdx.x;   // 16384 threads
    const int r  = i >> 10;                          // 0..15
    const int k4 = i & 1023;
    const float4 v = *(const float4*)&A[r * IN_F + k4 * 4];
    const int k = 4 * k4;
    g_At[(k + 0) * RANK + r] = 2.0f * v.x;
    g_At[(k + 1) * RANK + r] = 2.0f * v.y;
    g_At[(k + 2) * RANK + r] = 2.0f * v.z;
    g_At[(k + 3) * RANK + r] = 2.0f * v.w;
}

// ---------------- phase 1 ----------------
__global__ __launch_bounds__(256, 2)
void lora_phase1(const float* __restrict__ x) {
    __shared__ float  xs[2][KC][XPITCH];     // k-major x tile, padded rows
    __shared__ float4 as[2][KC * 4];         // At chunk, 16 floats per k

    const int tid  = threadIdx.x;
    const int lane = tid & 31;
    const int w    = tid >> 5;               // 8 warps
    const int ks   = blockIdx.x & (KSPLIT - 1);
    const int mt   = blockIdx.x >> 3;        // 0..127
    const int mbase = mt * MT;
    const int k0    = ks * KRANGE;

    const int sm  = tid >> 2;        // 0..63
    const int sk4 = tid & 3;         // 0..3
    const float* xrow = x + (size_t)(mbase + sm) * IN_F + k0;

    u64 acc[2][8];
    #pragma unroll
    for (int mp = 0; mp < 2; ++mp)
        #pragma unroll
        for (int rp = 0; rp < 8; ++rp) acc[mp][rp] = 0ull;

    float4 xr[4], ar;

    #pragma unroll
    for (int it = 0; it < 4; ++it)
        xr[it] = *(const float4*)(xrow + (sk4 + 4 * it) * 4);
    ar = *(const float4*)(g_At + (size_t)(k0) * RANK + tid * 4);

    #pragma unroll
    for (int it = 0; it < 4; ++it) {
        const int kk = 4 * (sk4 + 4 * it);
        xs[0][kk + 0][sm] = xr[it].x;
        xs[0][kk + 1][sm] = xr[it].y;
        xs[0][kk + 2][sm] = xr[it].z;
        xs[0][kk + 3][sm] = xr[it].w;
    }
    as[0][tid] = ar;
    __syncthreads();

    for (int c = 0; c < NCH; ++c) {
        const int buf = c & 1;

        if (c + 1 < NCH) {
            const int kc1 = (c + 1) * KC;
            #pragma unroll
            for (int it = 0; it < 4; ++it)
                xr[it] = *(const float4*)(xrow + kc1 + (sk4 + 4 * it) * 4);
            ar = *(const float4*)(g_At + (size_t)(k0 + kc1) * RANK + tid * 4);
        }

        #pragma unroll
        for (int kk = 0; kk < KC / 8; ++kk) {
            const int k = w * (KC / 8) + kk;
            const float2 xv = *(const float2*)&xs[buf][k][2 * lane];
            const u64 xd0 = pk2(xv.x, xv.x);
            const u64 xd1 = pk2(xv.y, xv.y);
            const ulonglong2* ap = (const ulonglong2*)&as[buf][k * 4];
            const ulonglong2 a01 = ap[0], a23 = ap[1];
            fma2(acc[0][0], xd0, a01.x); fma2(acc[1][0], xd1, a01.x);
            fma2(acc[0][1], xd0, a01.y); fma2(acc[1][1], xd1, a01.y);
            fma2(acc[0][2], xd0, a23.x); fma2(acc[1][2], xd1, a23.x);
            fma2(acc[0][3], xd0, a23.y); fma2(acc[1][3], xd1, a23.y);
            const ulonglong2 a45 = ap[2], a67 = ap[3];
            fma2(acc[0][4], xd0, a45.x); fma2(acc[1][4], xd1, a45.x);
            fma2(acc[0][5], xd0, a45.y); fma2(acc[1][5], xd1, a45.y);
            fma2(acc[0][6], xd0, a67.x); fma2(acc[1][6], xd1, a67.x);
            fma2(acc[0][7], xd0, a67.y); fma2(acc[1][7], xd1, a67.y);
        }

        if (c + 1 < NCH) {
            const int nb = (c + 1) & 1;
            #pragma unroll
            for (int it = 0; it < 4; ++it) {
                const int kk = 4 * (sk4 + 4 * it);
                xs[nb][kk + 0][sm] = xr[it].x;
                xs[nb][kk + 1][sm] = xr[it].y;
                xs[nb][kk + 2][sm] = xr[it].z;
                xs[nb][kk + 3][sm] = xr[it].w;
            }
            as[nb][tid] = ar;
        }
        __syncthreads();
    }

    // deterministic cross-warp reduction in smem (xs: 8448 floats >= 8192)
    float* tredf = &xs[0][0][0];
    #pragma unroll
    for (int mp = 0; mp < 2; ++mp) {
        const int m = 2 * lane + mp;
        const int base = w * 1024 + m * 16;
        #pragma unroll
        for (int rp = 0; rp < 8; ++rp) {
            const float2 f = up2(acc[mp][rp]);
            tredf[base + ((2 * rp     + lane) & 15)] = f.x;
            tredf[base + ((2 * rp + 1 + lane) & 15)] = f.y;
        }
    }
    __syncthreads();

    {
        const int m  = tid >> 2;
        const int r0 = (tid & 3) * 4;
        const int lw = m >> 1;
        float s[4];
        #pragma unroll
        for (int j = 0; j < 4; ++j) {
            const int cr = (r0 + j + lw) & 15;
            float v = 0.0f;
            #pragma unroll
            for (int w8 = 0; w8 < 8; ++w8)
                v += tredf[w8 * 1024 + m * 16 + cr];
            s[j] = v;
        }
        *(float4*)&g_tp[ks][mbase + m][r0] = make_float4(s[0], s[1], s[2], s[3]);
    }
}

// ---------------- phase 2 ----------------
// Thread owns 4 fixed consecutive o columns; B loaded ONCE into o-pair packed
// registers. t staged per 128-m slab in smem, pre-duplicated as (t,t) u64.
__global__ __launch_bounds__(256, 2)
void lora_phase2(const float* __restrict__ B,
                 const float* __restrict__ bias,
                 float* __restrict__ out) {
    __shared__ u64 t_d[MSLAB][RANK];     // 16 KB, (t,t) duplicated

    const int tid   = threadIdx.x;
    const int oblk  = blockIdx.x & 3;
    const int mslab = blockIdx.x >> 2;
    const int o0    = oblk * OTPB + tid * 4;
    const int m0    = mslab * MSLAB;

    // ---- load 4 B rows once, pack into o-pair f32x2 operands ----
    u64 bu[2][RANK];
    #pragma unroll
    for (int op = 0; op < 2; ++op) {
        float Bv0[RANK], Bv1[RANK];
        #pragma unroll
        for (int q = 0; q < 4; ++q) {
            *(float4*)&Bv0[4 * q] = *(const float4*)&B[(size_t)(o0 + 2 * op)     * RANK + 4 * q];
            *(float4*)&Bv1[4 * q] = *(const float4*)&B[(size_t)(o0 + 2 * op + 1) * RANK + 4 * q];
        }
        #pragma unroll
        for (int r = 0; r < RANK; ++r)
            bu[op][r] = pk2(Bv0[r], Bv1[r]);
    }
    const float4 bi4 = *(const float4*)&bias[o0];
    const u64 bias2[2] = { pk2(bi4.x, bi4.y), pk2(bi4.z, bi4.w) };

    // ---- stage t slab: sum KSPLIT partials, store duplicated ----
    #pragma unroll
    for (int j = 0; j < 2; ++j) {
        const int idx = tid * 2 + j;      // 0..511
        const int m = idx >> 2, q = idx & 3;
        float4 s = make_float4(0, 0, 0, 0);
        #pragma unroll
        for (int sl = 0; sl < KSPLIT; ++sl) {
            const float4 v = *(const float4*)&g_tp[sl][m0 + m][4 * q];
            s.x += v.x; s.y += v.y; s.z += v.z; s.w += v.w;
        }
        t_d[m][4 * q + 0] = pk2(s.x, s.x);
        t_d[m][4 * q + 1] = pk2(s.y, s.y);
        t_d[m][4 * q + 2] = pk2(s.z, s.z);
        t_d[m][4 * q + 3] = pk2(s.w, s.w);
    }
    __syncthreads();

    // ---- main loop over m: 8 broadcast LDS.128 + 32 fma2 + 1 STG.128 ----
    for (int m = 0; m < MSLAB; ++m) {
        const ulonglong2* tp = (const ulonglong2*)&t_d[m][0];
        u64 a0 = bias2[0], a1 = bias2[1];
        #pragma unroll
        for (int rp = 0; rp < 8; ++rp) {
            const ulonglong2 t2 = tp[rp];
            fma2(a0, t2.x, bu[0][2 * rp]);
            fma2(a1, t2.x, bu[1][2 * rp]);
            fma2(a0, t2.y, bu[0][2 * rp + 1]);
            fma2(a1, t2.y, bu[1][2 * rp + 1]);
        }
        const float2 lo = up2(a0), hi = up2(a1);
        *(float4*)&out[(size_t)(m0 + m) * OUT_F + o0] =
            make_float4(lo.x, lo.y, hi.x, hi.y);
    }
}

extern "C" void kernel_launch(void* const* d_in, const int* in_sizes, int n_in,
                              void* d_out, int out_size) {
    const float* x    = (const float*)d_in[0];   // [8192, 4096]
    const float* A    = (const float*)d_in[1];   // [16, 4096]
    const float* B    = (const float*)d_in[2];   // [4096, 16]
    const float* bias = (const float*)d_in[3];   // [4096]
    float* out = (float*)d_out;                  // [8192, 4096]

    prep_At<<<64, 256>>>(A);
    lora_phase1<<<(M_TOT / MT) * KSPLIT, 256>>>(x);
    lora_phase2<<<(OUT_F / OTPB) * (M_TOT / MSLAB), 256>>>(B, bias, out);
}